// round 1
// baseline (speedup 1.0000x reference)
#include <cuda_runtime.h>
#include <math.h>

// ---------------------------------------------------------------------------
// SelfAttention baseline (fp32 SIMT):
//   k = x@Wk + bk ; q = x@Wq + bq ; v = x@Wv + bv        (8192x1024x1024 each)
//   S[b] = k[b] @ q[b]^T                                  (2048x2048x1024, NT)
//   P = softmax_rows(S)
//   out[b] = P[b] @ v[b]                                  (2048x1024x2048, NN)
// ---------------------------------------------------------------------------

#define BB 4
#define NN_SEQ 2048
#define EE 1024
#define AA 1024

// Scratch (no cudaMalloc allowed): static device buffers.
__device__ float g_k[(size_t)BB * NN_SEQ * AA];
__device__ float g_q[(size_t)BB * NN_SEQ * AA];
__device__ float g_v[(size_t)BB * NN_SEQ * AA];
__device__ float g_s[(size_t)BB * NN_SEQ * NN_SEQ];

#define BM 128
#define BN 128
#define BK 16
#define TM 8
#define TN 8
#define NTHREADS 256
#define PAD 4   // smem row padding (keeps 16B alignment, breaks bank conflicts)

// C[M,N] = A[M,K] * op(B) (+ bias), batched over blockIdx.z via strides.
// TRANS_B=false: B is [K,N] row-major.  TRANS_B=true: B is [N,K] row-major.
template <bool TRANS_B, bool HAS_BIAS>
__global__ __launch_bounds__(NTHREADS)
void gemm_tile(const float* __restrict__ A, const float* __restrict__ B,
               const float* __restrict__ bias, float* __restrict__ C,
               int M, int N, int K,
               size_t sA, size_t sB, size_t sC)
{
    __shared__ float As[BK][BM + PAD];
    __shared__ float Bs[BK][BN + PAD];

    const int z = blockIdx.z;
    A += (size_t)z * sA;
    B += (size_t)z * sB;
    C += (size_t)z * sC;

    const int tid = threadIdx.x;
    const int tx = tid & 15;   // 0..15 -> column group
    const int ty = tid >> 4;   // 0..15 -> row group
    const int rowBase = blockIdx.y * BM;
    const int colBase = blockIdx.x * BN;

    float acc[TM][TN];
#pragma unroll
    for (int i = 0; i < TM; i++)
#pragma unroll
        for (int j = 0; j < TN; j++) acc[i][j] = 0.0f;

    for (int kt = 0; kt < K; kt += BK) {
        // ---- load A tile: 128 rows x 16 k, transposed into As[k][m] ----
#pragma unroll
        for (int l = 0; l < 2; l++) {
            int linear = tid + l * NTHREADS;       // 0..511
            int r  = linear >> 2;                  // 0..127
            int c4 = (linear & 3) * 4;             // 0,4,8,12
            float4 v = *reinterpret_cast<const float4*>(
                &A[(size_t)(rowBase + r) * K + kt + c4]);
            As[c4 + 0][r] = v.x;
            As[c4 + 1][r] = v.y;
            As[c4 + 2][r] = v.z;
            As[c4 + 3][r] = v.w;
        }
        if (TRANS_B) {
            // B is [N,K]: load 128 n-rows x 16 k, scatter into Bs[k][n]
#pragma unroll
            for (int l = 0; l < 2; l++) {
                int linear = tid + l * NTHREADS;
                int r  = linear >> 2;              // n index 0..127
                int c4 = (linear & 3) * 4;
                float4 v = *reinterpret_cast<const float4*>(
                    &B[(size_t)(colBase + r) * K + kt + c4]);
                Bs[c4 + 0][r] = v.x;
                Bs[c4 + 1][r] = v.y;
                Bs[c4 + 2][r] = v.z;
                Bs[c4 + 3][r] = v.w;
            }
        } else {
            // B is [K,N]: load 16 k-rows x 128 n directly into Bs[k][n]
#pragma unroll
            for (int l = 0; l < 2; l++) {
                int linear = tid + l * NTHREADS;
                int r = linear >> 5;               // k row 0..15
                int c = (linear & 31) * 4;         // col 0..124
                float4 v = *reinterpret_cast<const float4*>(
                    &B[(size_t)(kt + r) * N + colBase + c]);
                *reinterpret_cast<float4*>(&Bs[r][c]) = v;
            }
        }
        __syncthreads();

        // ---- compute 8x8 register tile ----
#pragma unroll
        for (int kk = 0; kk < BK; kk++) {
            float af[TM], bf[TN];
            *reinterpret_cast<float4*>(&af[0]) =
                *reinterpret_cast<const float4*>(&As[kk][ty * TM]);
            *reinterpret_cast<float4*>(&af[4]) =
                *reinterpret_cast<const float4*>(&As[kk][ty * TM + 4]);
            *reinterpret_cast<float4*>(&bf[0]) =
                *reinterpret_cast<const float4*>(&Bs[kk][tx * TN]);
            *reinterpret_cast<float4*>(&bf[4]) =
                *reinterpret_cast<const float4*>(&Bs[kk][tx * TN + 4]);
#pragma unroll
            for (int i = 0; i < TM; i++)
#pragma unroll
                for (int j = 0; j < TN; j++)
                    acc[i][j] = fmaf(af[i], bf[j], acc[i][j]);
        }
        __syncthreads();
    }

    // ---- epilogue ----
#pragma unroll
    for (int i = 0; i < TM; i++) {
        const size_t row = (size_t)(rowBase + ty * TM + i);
#pragma unroll
        for (int j = 0; j < TN; j += 4) {
            const int col = colBase + tx * TN + j;
            float4 v;
            v.x = acc[i][j + 0];
            v.y = acc[i][j + 1];
            v.z = acc[i][j + 2];
            v.w = acc[i][j + 3];
            if (HAS_BIAS) {
                v.x += bias[col + 0];
                v.y += bias[col + 1];
                v.z += bias[col + 2];
                v.w += bias[col + 3];
            }
            *reinterpret_cast<float4*>(&C[row * N + col]) = v;
        }
    }
}

// Row softmax over `cols` contiguous floats. One block per row, 256 threads.
__global__ __launch_bounds__(256)
void softmax_rows(float* __restrict__ S, int cols)
{
    float* p = S + (size_t)blockIdx.x * cols;
    const int tid  = threadIdx.x;
    const int lane = tid & 31;
    const int wid  = tid >> 5;
    __shared__ float red[8];
    __shared__ float bval;

    // pass 1: max
    float m = -INFINITY;
    for (int c = tid; c < cols; c += 256) m = fmaxf(m, p[c]);
#pragma unroll
    for (int o = 16; o > 0; o >>= 1) m = fmaxf(m, __shfl_xor_sync(0xffffffffu, m, o));
    if (lane == 0) red[wid] = m;
    __syncthreads();
    if (tid == 0) {
        float t = red[0];
#pragma unroll
        for (int i = 1; i < 8; i++) t = fmaxf(t, red[i]);
        bval = t;
    }
    __syncthreads();
    const float rowmax = bval;
    __syncthreads();

    // pass 2: exp + sum
    float s = 0.0f;
    for (int c = tid; c < cols; c += 256) {
        float e = expf(p[c] - rowmax);
        p[c] = e;
        s += e;
    }
#pragma unroll
    for (int o = 16; o > 0; o >>= 1) s += __shfl_xor_sync(0xffffffffu, s, o);
    if (lane == 0) red[wid] = s;
    __syncthreads();
    if (tid == 0) {
        float t = 0.0f;
#pragma unroll
        for (int i = 0; i < 8; i++) t += red[i];
        bval = t;
    }
    __syncthreads();
    const float inv = 1.0f / bval;

    // pass 3: normalize
    for (int c = tid; c < cols; c += 256) p[c] *= inv;
}

extern "C" void kernel_launch(void* const* d_in, const int* in_sizes, int n_in,
                              void* d_out, int out_size)
{
    (void)in_sizes; (void)n_in; (void)out_size;
    const float* x  = (const float*)d_in[0];
    const float* Wk = (const float*)d_in[1];
    const float* bk = (const float*)d_in[2];
    const float* Wq = (const float*)d_in[3];
    const float* bq = (const float*)d_in[4];
    const float* Wv = (const float*)d_in[5];
    const float* bv = (const float*)d_in[6];
    float* out = (float*)d_out;

    float *kp, *qp, *vp, *sp;
    cudaGetSymbolAddress((void**)&kp, g_k);
    cudaGetSymbolAddress((void**)&qp, g_q);
    cudaGetSymbolAddress((void**)&vp, g_v);
    cudaGetSymbolAddress((void**)&sp, g_s);

    const int Mflat = BB * NN_SEQ;  // 8192

    // projections: [8192,1024] @ [1024,1024] + bias  (NN, flat over batch)
    dim3 gProj(AA / BN, Mflat / BM, 1);
    gemm_tile<false, true><<<gProj, NTHREADS>>>(x, Wk, bk, kp, Mflat, AA, EE, 0, 0, 0);
    gemm_tile<false, true><<<gProj, NTHREADS>>>(x, Wq, bq, qp, Mflat, AA, EE, 0, 0, 0);
    gemm_tile<false, true><<<gProj, NTHREADS>>>(x, Wv, bv, vp, Mflat, AA, EE, 0, 0, 0);

    // scores: S[b] = k[b] @ q[b]^T  (NT, per batch)
    dim3 gScore(NN_SEQ / BN, NN_SEQ / BM, BB);
    gemm_tile<true, false><<<gScore, NTHREADS>>>(
        kp, qp, nullptr, sp, NN_SEQ, NN_SEQ, AA,
        (size_t)NN_SEQ * AA, (size_t)NN_SEQ * AA, (size_t)NN_SEQ * NN_SEQ);

    // softmax over rows of S
    softmax_rows<<<BB * NN_SEQ, 256>>>(sp, NN_SEQ);

    // out[b] = P[b] @ v[b]  (NN, per batch)
    dim3 gOut(AA / BN, NN_SEQ / BM, BB);
    gemm_tile<false, false><<<gOut, NTHREADS>>>(
        sp, vp, nullptr, out, NN_SEQ, AA, NN_SEQ,
        (size_t)NN_SEQ * NN_SEQ, (size_t)NN_SEQ * AA, (size_t)NN_SEQ * AA);
}

// round 3
// speedup vs baseline: 2.8313x; 2.8313x over previous
#include <cuda_runtime.h>
#include <cuda_bf16.h>
#include <math.h>
#include <cstdint>
#include <cstddef>

// ---------------------------------------------------------------------------
// SelfAttention via mma.sync (HMMA) bf16x3 hi/lo-split GEMMs, fp32 accumulate.
//   k = x@Wk+bk ; q = x@Wq+bq ; v = x@Wv+bv
//   S[b] = k[b] @ q[b]^T ; P = softmax(S) ; out[b] = P[b] @ v[b]
// All GEMMs: D[m,n] = sum_k A[m,k]*B[n,k]  (both operands K-contiguous).
// ---------------------------------------------------------------------------

#define BB 4
#define SEQ 2048
#define EMB 1024

// ------------------------- scratch (static device) -------------------------
__device__ __nv_bfloat16 g_xh[(size_t)BB*SEQ*EMB], g_xl[(size_t)BB*SEQ*EMB];
__device__ __nv_bfloat16 g_wkh[(size_t)EMB*EMB], g_wkl[(size_t)EMB*EMB];
__device__ __nv_bfloat16 g_wqh[(size_t)EMB*EMB], g_wql[(size_t)EMB*EMB];
__device__ __nv_bfloat16 g_wvh[(size_t)EMB*EMB], g_wvl[(size_t)EMB*EMB];
__device__ __nv_bfloat16 g_kh[(size_t)BB*SEQ*EMB], g_kl[(size_t)BB*SEQ*EMB];
__device__ __nv_bfloat16 g_qh[(size_t)BB*SEQ*EMB], g_ql[(size_t)BB*SEQ*EMB];
__device__ float         g_v [(size_t)BB*SEQ*EMB];
__device__ __nv_bfloat16 g_vth[(size_t)BB*SEQ*EMB], g_vtl[(size_t)BB*SEQ*EMB];
__device__ float         g_s [(size_t)BB*SEQ*SEQ];
__device__ __nv_bfloat16 g_ph[(size_t)BB*SEQ*SEQ], g_pl[(size_t)BB*SEQ*SEQ];

// ------------------------- helpers -----------------------------------------
__device__ __forceinline__ uint32_t smem_to_u32(const void* p) {
    uint32_t a;
    asm("{ .reg .u64 t; cvta.to.shared.u64 t, %1; cvt.u32.u64 %0, t; }"
        : "=r"(a) : "l"(p));
    return a;
}
#define SWZ128(o) ((o) ^ (((o) >> 3) & 0x70))

__device__ __forceinline__ void cp16(uint32_t dst, const void* src) {
    unsigned long long g = (unsigned long long)__cvta_generic_to_global(src);
    asm volatile("cp.async.cg.shared.global [%0], [%1], 16;" :: "r"(dst), "l"(g));
}

__device__ __forceinline__ void ldsm4(uint32_t addr, uint32_t* r) {
    asm volatile("ldmatrix.sync.aligned.m8n8.x4.shared.b16 {%0,%1,%2,%3}, [%4];"
                 : "=r"(r[0]), "=r"(r[1]), "=r"(r[2]), "=r"(r[3]) : "r"(addr));
}

__device__ __forceinline__ void mma16816(float* d, const uint32_t* a, const uint32_t* b) {
    asm volatile(
        "mma.sync.aligned.m16n8k16.row.col.f32.bf16.bf16.f32 "
        "{%0,%1,%2,%3}, {%4,%5,%6,%7}, {%8,%9}, {%0,%1,%2,%3};"
        : "+f"(d[0]), "+f"(d[1]), "+f"(d[2]), "+f"(d[3])
        : "r"(a[0]), "r"(a[1]), "r"(a[2]), "r"(a[3]), "r"(b[0]), "r"(b[1]));
}

// ------------------------- conversion kernels ------------------------------
__global__ __launch_bounds__(256)
void split_kernel(const float4* __restrict__ in,
                  __nv_bfloat162* __restrict__ hi, __nv_bfloat162* __restrict__ lo,
                  size_t n4)
{
    size_t i = (size_t)blockIdx.x * blockDim.x + threadIdx.x;
    if (i >= n4) return;
    float4 v = in[i];
    __nv_bfloat16 hx = __float2bfloat16(v.x), hy = __float2bfloat16(v.y);
    __nv_bfloat16 hz = __float2bfloat16(v.z), hw = __float2bfloat16(v.w);
    __nv_bfloat16 lx = __float2bfloat16(v.x - __bfloat162float(hx));
    __nv_bfloat16 ly = __float2bfloat16(v.y - __bfloat162float(hy));
    __nv_bfloat16 lz = __float2bfloat16(v.z - __bfloat162float(hz));
    __nv_bfloat16 lw = __float2bfloat16(v.w - __bfloat162float(hw));
    hi[2*i]   = __nv_bfloat162(hx, hy);
    hi[2*i+1] = __nv_bfloat162(hz, hw);
    lo[2*i]   = __nv_bfloat162(lx, ly);
    lo[2*i+1] = __nv_bfloat162(lz, lw);
}

// in[z]: [R,C] fp32 -> out[z]: [C,R] bf16 hi/lo
__global__ __launch_bounds__(256)
void transpose_split(const float* __restrict__ in,
                     __nv_bfloat16* __restrict__ oh, __nv_bfloat16* __restrict__ ol,
                     int R, int C, size_t sIn, size_t sOut)
{
    __shared__ float t[32][33];
    const size_t zi = (size_t)blockIdx.z * sIn;
    const size_t zo = (size_t)blockIdx.z * sOut;
    const int c0 = blockIdx.x * 32, r0 = blockIdx.y * 32;
    const int tx = threadIdx.x, ty = threadIdx.y;
#pragma unroll
    for (int i = 0; i < 32; i += 8)
        t[ty + i][tx] = in[zi + (size_t)(r0 + ty + i) * C + c0 + tx];
    __syncthreads();
#pragma unroll
    for (int i = 0; i < 32; i += 8) {
        float v = t[tx][ty + i];
        size_t o = zo + (size_t)(c0 + ty + i) * R + r0 + tx;
        __nv_bfloat16 h = __float2bfloat16(v);
        oh[o] = h;
        ol[o] = __float2bfloat16(v - __bfloat162float(h));
    }
}

// ------------------------- softmax + split ---------------------------------
__global__ __launch_bounds__(256)
void softmax_split(float* __restrict__ S,
                   __nv_bfloat16* __restrict__ Ph, __nv_bfloat16* __restrict__ Pl)
{
    float* p = S + (size_t)blockIdx.x * SEQ;
    __nv_bfloat16* ph = Ph + (size_t)blockIdx.x * SEQ;
    __nv_bfloat16* pl = Pl + (size_t)blockIdx.x * SEQ;
    const int tid = threadIdx.x, lane = tid & 31, wid = tid >> 5;
    __shared__ float red[8];
    __shared__ float bval;

    float m = -INFINITY;
    for (int c = tid; c < SEQ; c += 256) m = fmaxf(m, p[c]);
#pragma unroll
    for (int o = 16; o > 0; o >>= 1) m = fmaxf(m, __shfl_xor_sync(0xffffffffu, m, o));
    if (lane == 0) red[wid] = m;
    __syncthreads();
    if (tid == 0) {
        float t = red[0];
#pragma unroll
        for (int i = 1; i < 8; i++) t = fmaxf(t, red[i]);
        bval = t;
    }
    __syncthreads();
    const float rowmax = bval;
    __syncthreads();

    float s = 0.0f;
    for (int c = tid; c < SEQ; c += 256) {
        float e = __expf(p[c] - rowmax);
        p[c] = e;
        s += e;
    }
#pragma unroll
    for (int o = 16; o > 0; o >>= 1) s += __shfl_xor_sync(0xffffffffu, s, o);
    if (lane == 0) red[wid] = s;
    __syncthreads();
    if (tid == 0) {
        float t = 0.0f;
#pragma unroll
        for (int i = 0; i < 8; i++) t += red[i];
        bval = t;
    }
    __syncthreads();
    const float inv = 1.0f / bval;

    for (int c = tid; c < SEQ; c += 256) {
        float v = p[c] * inv;
        __nv_bfloat16 h = __float2bfloat16(v);
        ph[c] = h;
        pl[c] = __float2bfloat16(v - __bfloat162float(h));
    }
}

// ------------------------- HMMA bf16x3 GEMM ---------------------------------
// 128x128 CTA tile, 8 warps (2 row x 4 col), warp tile 64x32.
// K chunk 64 bf16 (128B SW128 rows), 2-stage cp.async pipeline.
// SMEM per stage: Ah(16K) Al(16K) Bh(16K) Bl(16K) = 64KB; 2 stages.
#define STAGE_BYTES 65536
#define GEMM_SMEM (2 * STAGE_BYTES + 1024)

template <int OUT_SPLIT>
__global__ void __launch_bounds__(256, 1)
gemm_bf16x3(const __nv_bfloat16* __restrict__ Ah, const __nv_bfloat16* __restrict__ Al,
            const __nv_bfloat16* __restrict__ Bh, const __nv_bfloat16* __restrict__ Bl,
            const float* __restrict__ bias,
            float* __restrict__ Cf,
            __nv_bfloat16* __restrict__ Ch, __nv_bfloat16* __restrict__ Cl,
            int M, int N, int K,
            size_t sA, size_t sB, size_t sC)
{
    extern __shared__ char smem[];
    const uint32_t sb = (smem_to_u32(smem) + 1023u) & ~1023u;
    const int tid = threadIdx.x;
    const int wid = tid >> 5;
    const int lane = tid & 31;
    const int z = blockIdx.z;
    const int rowBase = blockIdx.y * 128;
    const int colBase = blockIdx.x * 128;
    const int NC = K >> 6;

    const int warpRow = wid & 1;   // 0..1 -> 64 rows each
    const int warpCol = wid >> 1;  // 0..3 -> 32 cols each

    const __nv_bfloat16* aH = Ah + (size_t)z * sA + (size_t)rowBase * K;
    const __nv_bfloat16* aL = Al + (size_t)z * sA + (size_t)rowBase * K;
    const __nv_bfloat16* bH = Bh + (size_t)z * sB + (size_t)colBase * K;
    const __nv_bfloat16* bL = Bl + (size_t)z * sB + (size_t)colBase * K;

    // cp.async mapping: 4 tiles x 1024 granules(16B) / 256 threads
    const int grow0 = tid >> 3;           // row for granule i: grow0 + i*32
    const int kgB   = (tid & 7) * 16;     // byte offset within 128B row
    const int kgE   = (tid & 7) * 8;      // element offset (bf16)

    auto load_chunk = [&](int stage, int chunk) {
        const uint32_t base = sb + stage * STAGE_BYTES;
        const int koff = chunk * 64 + kgE;
#pragma unroll
        for (int i = 0; i < 4; i++) {
            const int row = grow0 + i * 32;
            const uint32_t so = SWZ128((uint32_t)(row * 128 + kgB));
            const size_t ge = (size_t)row * K + koff;
            cp16(base +         so, aH + ge);
            cp16(base + 16384 + so, aL + ge);
            cp16(base + 32768 + so, bH + ge);
            cp16(base + 49152 + so, bL + ge);
        }
        asm volatile("cp.async.commit_group;" ::: "memory");
    };

    float acc[4][4][4];
#pragma unroll
    for (int i = 0; i < 4; i++)
#pragma unroll
        for (int j = 0; j < 4; j++)
#pragma unroll
            for (int l = 0; l < 4; l++) acc[i][j][l] = 0.0f;

    // ldmatrix address components (per lane)
    const int aRow = warpRow * 64 + (lane & 15);   // + mt*16
    const int aKB  = (lane >> 4) * 16;             // k-half byte offset
    const int bRow = warpCol * 32 + ((lane >> 3) >> 1) * 8 + (lane & 7); // + pair*16
    const int bKB  = ((lane >> 3) & 1) * 16;

    load_chunk(0, 0);

    for (int c = 0; c < NC; c++) {
        const int s = c & 1;
        if (c + 1 < NC) {
            load_chunk(s ^ 1, c + 1);
            asm volatile("cp.async.wait_group 1;" ::: "memory");
        } else {
            asm volatile("cp.async.wait_group 0;" ::: "memory");
        }
        __syncthreads();

        const uint32_t st = sb + s * STAGE_BYTES;
#pragma unroll
        for (int ks = 0; ks < 4; ks++) {
            uint32_t ah[4][4], al[4][4], bh[4][2], bl[4][2];
#pragma unroll
            for (int mt = 0; mt < 4; mt++) {
                const uint32_t sw = SWZ128(
                    (uint32_t)((aRow + mt * 16) * 128 + ks * 32 + aKB));
                ldsm4(st + sw, ah[mt]);
                ldsm4(st + 16384 + sw, al[mt]);
            }
#pragma unroll
            for (int p = 0; p < 2; p++) {
                const uint32_t sw = SWZ128(
                    (uint32_t)((bRow + p * 16) * 128 + ks * 32 + bKB));
                uint32_t t[4];
                ldsm4(st + 32768 + sw, t);
                bh[2*p][0] = t[0]; bh[2*p][1] = t[1];
                bh[2*p+1][0] = t[2]; bh[2*p+1][1] = t[3];
                ldsm4(st + 49152 + sw, t);
                bl[2*p][0] = t[0]; bl[2*p][1] = t[1];
                bl[2*p+1][0] = t[2]; bl[2*p+1][1] = t[3];
            }
#pragma unroll
            for (int mt = 0; mt < 4; mt++)
#pragma unroll
                for (int nt = 0; nt < 4; nt++) {
                    mma16816(acc[mt][nt], ah[mt], bh[nt]);
                    mma16816(acc[mt][nt], ah[mt], bl[nt]);
                    mma16816(acc[mt][nt], al[mt], bh[nt]);
                }
        }
        __syncthreads();
    }

    // ---- epilogue ----
    const int lr = lane >> 2;          // 0..7
    const int lc = (lane & 3) * 2;     // 0,2,4,6
#pragma unroll
    for (int mt = 0; mt < 4; mt++) {
        const int r0 = rowBase + warpRow * 64 + mt * 16 + lr;
#pragma unroll
        for (int nt = 0; nt < 4; nt++) {
            const int c0 = colBase + warpCol * 32 + nt * 8 + lc;
            float v0 = acc[mt][nt][0], v1 = acc[mt][nt][1];
            float v2 = acc[mt][nt][2], v3 = acc[mt][nt][3];
            if (bias) {
                const float b0 = bias[c0], b1 = bias[c0 + 1];
                v0 += b0; v1 += b1; v2 += b0; v3 += b1;
            }
            if (OUT_SPLIT == 0) {
                float* base = Cf + (size_t)z * sC;
                *reinterpret_cast<float2*>(&base[(size_t)r0 * N + c0]) =
                    make_float2(v0, v1);
                *reinterpret_cast<float2*>(&base[(size_t)(r0 + 8) * N + c0]) =
                    make_float2(v2, v3);
            } else {
                __nv_bfloat16 h0 = __float2bfloat16(v0);
                __nv_bfloat16 h1 = __float2bfloat16(v1);
                __nv_bfloat16 h2 = __float2bfloat16(v2);
                __nv_bfloat16 h3 = __float2bfloat16(v3);
                __nv_bfloat162 hlo01(__float2bfloat16(v0 - __bfloat162float(h0)),
                                     __float2bfloat16(v1 - __bfloat162float(h1)));
                __nv_bfloat162 hlo23(__float2bfloat16(v2 - __bfloat162float(h2)),
                                     __float2bfloat16(v3 - __bfloat162float(h3)));
                __nv_bfloat16* chb = Ch + (size_t)z * sC;
                __nv_bfloat16* clb = Cl + (size_t)z * sC;
                *reinterpret_cast<__nv_bfloat162*>(&chb[(size_t)r0 * N + c0]) =
                    __nv_bfloat162(h0, h1);
                *reinterpret_cast<__nv_bfloat162*>(&chb[(size_t)(r0 + 8) * N + c0]) =
                    __nv_bfloat162(h2, h3);
                *reinterpret_cast<__nv_bfloat162*>(&clb[(size_t)r0 * N + c0]) = hlo01;
                *reinterpret_cast<__nv_bfloat162*>(&clb[(size_t)(r0 + 8) * N + c0]) = hlo23;
            }
        }
    }
}

// ------------------------- launch ------------------------------------------
extern "C" void kernel_launch(void* const* d_in, const int* in_sizes, int n_in,
                              void* d_out, int out_size)
{
    (void)in_sizes; (void)n_in; (void)out_size;
    const float* x  = (const float*)d_in[0];
    const float* Wk = (const float*)d_in[1];
    const float* bk = (const float*)d_in[2];
    const float* Wq = (const float*)d_in[3];
    const float* bq = (const float*)d_in[4];
    const float* Wv = (const float*)d_in[5];
    const float* bv = (const float*)d_in[6];
    float* out = (float*)d_out;

    __nv_bfloat16 *xh, *xl, *wkh, *wkl, *wqh, *wql, *wvh, *wvl;
    __nv_bfloat16 *kh, *kl, *qh, *ql, *vth, *vtl, *ph, *pl;
    float *vf, *sf;
    cudaGetSymbolAddress((void**)&xh, g_xh);   cudaGetSymbolAddress((void**)&xl, g_xl);
    cudaGetSymbolAddress((void**)&wkh, g_wkh); cudaGetSymbolAddress((void**)&wkl, g_wkl);
    cudaGetSymbolAddress((void**)&wqh, g_wqh); cudaGetSymbolAddress((void**)&wql, g_wql);
    cudaGetSymbolAddress((void**)&wvh, g_wvh); cudaGetSymbolAddress((void**)&wvl, g_wvl);
    cudaGetSymbolAddress((void**)&kh, g_kh);   cudaGetSymbolAddress((void**)&kl, g_kl);
    cudaGetSymbolAddress((void**)&qh, g_qh);   cudaGetSymbolAddress((void**)&ql, g_ql);
    cudaGetSymbolAddress((void**)&vf, g_v);
    cudaGetSymbolAddress((void**)&vth, g_vth); cudaGetSymbolAddress((void**)&vtl, g_vtl);
    cudaGetSymbolAddress((void**)&sf, g_s);
    cudaGetSymbolAddress((void**)&ph, g_ph);   cudaGetSymbolAddress((void**)&pl, g_pl);

    cudaFuncSetAttribute(gemm_bf16x3<0>,
                         cudaFuncAttributeMaxDynamicSharedMemorySize, GEMM_SMEM);
    cudaFuncSetAttribute(gemm_bf16x3<1>,
                         cudaFuncAttributeMaxDynamicSharedMemorySize, GEMM_SMEM);

    const int Mflat = BB * SEQ;  // 8192

    // x -> bf16 hi/lo
    {
        size_t n4 = (size_t)Mflat * EMB / 4;
        split_kernel<<<(unsigned)((n4 + 255) / 256), 256>>>(
            (const float4*)x, (__nv_bfloat162*)xh, (__nv_bfloat162*)xl, n4);
    }
    // W[E,A] -> W^T[A,E] hi/lo
    transpose_split<<<dim3(32, 32, 1), dim3(32, 8)>>>(Wk, wkh, wkl, EMB, EMB, 0, 0);
    transpose_split<<<dim3(32, 32, 1), dim3(32, 8)>>>(Wq, wqh, wql, EMB, EMB, 0, 0);
    transpose_split<<<dim3(32, 32, 1), dim3(32, 8)>>>(Wv, wvh, wvl, EMB, EMB, 0, 0);

    // projections: [8192,1024] x W^T
    dim3 gProj(EMB / 128, Mflat / 128, 1);
    gemm_bf16x3<1><<<gProj, 256, GEMM_SMEM>>>(xh, xl, wkh, wkl, bk,
                                              nullptr, kh, kl,
                                              Mflat, EMB, EMB, 0, 0, 0);
    gemm_bf16x3<1><<<gProj, 256, GEMM_SMEM>>>(xh, xl, wqh, wql, bq,
                                              nullptr, qh, ql,
                                              Mflat, EMB, EMB, 0, 0, 0);
    gemm_bf16x3<0><<<gProj, 256, GEMM_SMEM>>>(xh, xl, wvh, wvl, bv,
                                              vf, nullptr, nullptr,
                                              Mflat, EMB, EMB, 0, 0, 0);

    // v[b] [2048,1024] -> v^T[b] [1024,2048] hi/lo
    transpose_split<<<dim3(EMB / 32, SEQ / 32, BB), dim3(32, 8)>>>(
        vf, vth, vtl, SEQ, EMB, (size_t)SEQ * EMB, (size_t)SEQ * EMB);

    // scores: S[b] = k[b] @ q[b]^T
    dim3 gS(SEQ / 128, SEQ / 128, BB);
    gemm_bf16x3<0><<<gS, 256, GEMM_SMEM>>>(kh, kl, qh, ql, nullptr,
                                           sf, nullptr, nullptr,
                                           SEQ, SEQ, EMB,
                                           (size_t)SEQ * EMB, (size_t)SEQ * EMB,
                                           (size_t)SEQ * SEQ);

    // softmax rows + split to bf16 hi/lo
    softmax_split<<<BB * SEQ, 256>>>(sf, ph, pl);

    // out[b] = P[b] @ v[b]   (B operand = v^T, K-contiguous)
    dim3 gO(EMB / 128, SEQ / 128, BB);
    gemm_bf16x3<0><<<gO, 256, GEMM_SMEM>>>(ph, pl, vth, vtl, nullptr,
                                           out, nullptr, nullptr,
                                           SEQ, EMB, SEQ,
                                           (size_t)SEQ * SEQ, (size_t)SEQ * EMB,
                                           (size_t)SEQ * EMB);
}